// round 2
// baseline (speedup 1.0000x reference)
#include <cuda_runtime.h>
#include <cstdint>

typedef unsigned long long u64;

#define Bn 64
#define Gn 200
#define QT 10

// ---------------- scratch (static device arrays; no allocation) ----------------
__device__ float g_Q[Bn * Gn * 128];          // [b][g][h*16+k]
__device__ float g_K[Bn * Gn * 128];          // [b][g][h*16+k]
__device__ float g_Vt[Bn * 128 * Gn];         // [b][h*16+v][g]

// ---------------- packed f32x2 helpers ----------------
__device__ __forceinline__ u64 fma2(u64 a, u64 b, u64 c) {
    u64 d; asm("fma.rn.f32x2 %0, %1, %2, %3;" : "=l"(d) : "l"(a), "l"(b), "l"(c)); return d;
}
__device__ __forceinline__ u64 pk(float lo, float hi) {
    u64 d; asm("mov.b64 %0, {%1, %2};" : "=l"(d) : "f"(lo), "f"(hi)); return d;
}
__device__ __forceinline__ float2 up(u64 a) {
    float2 r; asm("mov.b64 {%0, %1}, %2;" : "=f"(r.x), "=f"(r.y) : "l"(a)); return r;
}
__device__ __forceinline__ float hadd(u64 a) { float2 r = up(a); return r.x + r.y; }

// ================= kernel 1: QKV projections =================
// grid 512 = 64 b * 8 gtiles(25 each), 256 threads.
// smem: x[25][128] + Wt[128][128] (transposed + chunk-XOR swizzled)
#define SMEM1 ((3200 + 16384) * 4)

__global__ __launch_bounds__(256) void qkv_kernel(
    const float* __restrict__ h_em, const float* __restrict__ Wq,
    const float* __restrict__ Wk, const float* __restrict__ Wv)
{
    extern __shared__ float sm1[];
    float* xs  = sm1;          // 3200 floats
    float* wst = sm1 + 3200;   // 16384 floats: [row=h*16+k][d], swizzled

    int t = threadIdx.x;
    int b = blockIdx.x >> 3;
    int g0 = (blockIdx.x & 7) * 25;

    const float4* xsrc = (const float4*)(h_em + (b * Gn + g0) * 128);
    for (int i = t; i < 800; i += 256) ((float4*)xs)[i] = xsrc[i];

    const float* Wp[3] = {Wq, Wk, Wv};
    #pragma unroll 1
    for (int w = 0; w < 3; w++) {
        const float* W = Wp[w];
        __syncthreads();
        // W[h][d][k] -> wst[h*16+k][d], 16B-chunk XOR swizzle by row&7
        for (int idx = t; idx < 16384; idx += 256) {
            int hh = idx >> 11, d = (idx >> 4) & 127, k = idx & 15;
            int row = hh * 16 + k;
            int word = (((d >> 2) ^ (row & 7)) << 2) | (d & 3);
            wst[row * 128 + word] = W[idx];
        }
        __syncthreads();
        for (int u = t; u < 3200; u += 256) {
            int pos = u >> 7, row = u & 127;
            const ulonglong2* x4 = (const ulonglong2*)(xs + pos * 128);
            const ulonglong2* w4 = (const ulonglong2*)(wst + row * 128);
            int sw = row & 7;
            u64 a0 = 0ull, a1 = 0ull;
            #pragma unroll
            for (int c = 0; c < 32; c += 2) {
                ulonglong2 xv0 = x4[c],      xv1 = x4[c + 1];
                ulonglong2 wv0 = w4[c ^ sw], wv1 = w4[(c + 1) ^ sw];
                a0 = fma2(xv0.x, wv0.x, a0); a0 = fma2(xv0.y, wv0.y, a0);
                a1 = fma2(xv1.x, wv1.x, a1); a1 = fma2(xv1.y, wv1.y, a1);
            }
            float r = hadd(a0) + hadd(a1);
            int g = g0 + pos, hh = row >> 4, k = row & 15;
            if (w == 0)      g_Q[(b * Gn + g) * 128 + row] = r;
            else if (w == 1) g_K[(b * Gn + g) * 128 + row] = r;
            else             g_Vt[((b * 8 + hh) * 16 + k) * Gn + g] = r;
        }
    }
}

// ================= kernel 2: fused qk + route + MLP + softmax + AV + Wout =================
// grid (20, 64) = (q-tile of 10, b); 512 threads; 206528 B smem (1 CTA/SM)
#define SMEM2 206528

__global__ __launch_bounds__(512) void main_kernel(
    const float* __restrict__ route, const float* __restrict__ W1,
    const float* __restrict__ b1, const float* __restrict__ W2,
    const float* __restrict__ b2, const float* __restrict__ Wo,
    float* __restrict__ out, float* __restrict__ out_route)
{
    extern __shared__ char smraw[];
    float* Ksm    = (float*)smraw;           // 25600 f : [g][h*16+k] swizzled by (g>>1)&7
    float* L      = Ksm + 25600;             // 16000 f : logits/probs [q][h][g]
    float* Qsm    = L + 16000;               // 1280 f  : [q][h*16+k]
    float* hp     = Qsm + 1280;              // 5120 f  : head partials [s][hv][q]
    u64*   headsd = (u64*)(hp + 5120);       // 1280 u64: duplicated heads [q][hv]
    u64*   W1d    = headsd + 1280;           // 384 u64
    u64*   W2d    = W1d + 384;               // 128 u64
    u64*   b1d    = W2d + 128;               // 16
    u64*   b2d    = b1d + 16;                // 8

    int t  = threadIdx.x;
    int b  = blockIdx.y;
    int q0 = blockIdx.x * QT;

    // ---- phase 0: stage K (swizzled), Q, dup weight tables ----
    const float4* Ks = (const float4*)(g_K + b * Gn * 128);
    for (int i4 = t; i4 < 6400; i4 += 512) {
        int g = i4 >> 5, c4 = i4 & 31;
        ((float4*)Ksm)[g * 32 + (c4 ^ ((g >> 1) & 7))] = Ks[i4];
    }
    const float4* Qs = (const float4*)(g_Q + (b * Gn + q0) * 128);
    for (int i4 = t; i4 < 320; i4 += 512) ((float4*)Qsm)[i4] = Qs[i4];
    if (t < 384) W1d[t] = pk(W1[t], W1[t]);
    if (t < 128) W2d[t] = pk(W2[t], W2[t]);
    if (t < 16)  b1d[t] = pk(b1[t], b1[t]);
    if (t < 8)   b2d[t] = pk(b2[t], b2[t]);
    __syncthreads();

    // ---- phase 1: per (q, g-pair): qk dots + route stream + packed MLP -> logits ----
    for (int u = t; u < 1000; u += 512) {
        int q  = u / 100;
        int gp = u - q * 100;
        int g  = gp * 2;
        int sw = gp & 7;
        u64 x2[24];
        const ulonglong2* Qr = (const ulonglong2*)(Qsm + q * 128);
        const ulonglong2* K0 = (const ulonglong2*)(Ksm + g * 128);
        const ulonglong2* K1 = (const ulonglong2*)(Ksm + (g + 1) * 128);
        #pragma unroll
        for (int h = 0; h < 8; h++) {
            u64 a0 = 0ull, a1 = 0ull;
            #pragma unroll
            for (int c = 0; c < 4; c++) {
                int ci = h * 4 + c;
                ulonglong2 qv = Qr[ci];
                ulonglong2 k0 = K0[ci ^ sw];
                ulonglong2 k1 = K1[ci ^ sw];
                a0 = fma2(qv.x, k0.x, a0); a0 = fma2(qv.y, k0.y, a0);
                a1 = fma2(qv.x, k1.x, a1); a1 = fma2(qv.y, k1.y, a1);
            }
            x2[h] = pk(hadd(a0), hadd(a1));
        }
        long long ridx = (long long)(b * Gn + (q0 + q)) * Gn + g;
        const float* rp = route + ridx;
        #pragma unroll
        for (int r = 0; r < 16; r++)
            x2[8 + r] = *(const u64*)(rp + (long long)r * 2560000);
        if (out_route) {
            float* wpp = out_route + ridx;
            #pragma unroll
            for (int r = 0; r < 16; r++)
                *(u64*)(wpp + (long long)r * 2560000) = x2[8 + r];
        }
        u64 oacc[8];
        #pragma unroll
        for (int h = 0; h < 8; h++) oacc[h] = b2d[h];
        #pragma unroll
        for (int j = 0; j < 16; j++) {
            u64 a = b1d[j];
            #pragma unroll
            for (int i = 0; i < 24; i++) a = fma2(x2[i], W1d[j * 24 + i], a);
            float2 hv = up(a);
            a = pk(fmaxf(hv.x, 0.f), fmaxf(hv.y, 0.f));   // relu
            #pragma unroll
            for (int h = 0; h < 8; h++) oacc[h] = fma2(a, W2d[h * 16 + j], oacc[h]);
        }
        #pragma unroll
        for (int h = 0; h < 8; h++) *(u64*)(L + q * 1600 + h * 200 + g) = oacc[h];
    }
    __syncthreads();

    // ---- phase 2: softmax over g, one warp per (q,h) row ----
    {
        int warp = t >> 5, lane = t & 31;
        for (int row = warp; row < 80; row += 16) {
            float* Lr = L + (row >> 3) * 1600 + (row & 7) * 200;
            float m = -1e30f;
            for (int i = lane; i < 200; i += 32) m = fmaxf(m, Lr[i]);
            #pragma unroll
            for (int o = 16; o > 0; o >>= 1) m = fmaxf(m, __shfl_xor_sync(0xffffffffu, m, o));
            float s = 0.f;
            for (int i = lane; i < 200; i += 32) { float e = __expf(Lr[i] - m); Lr[i] = e; s += e; }
            #pragma unroll
            for (int o = 16; o > 0; o >>= 1) s += __shfl_xor_sync(0xffffffffu, s, o);
            float inv = 1.f / s;
            for (int i = lane; i < 200; i += 32) Lr[i] *= inv;
        }
    }
    __syncthreads();

    // ---- phase 3: heads[q][hv] = sum_g p[q][h][g] * Vt[hv][g] ----
    {
        int s = t >> 7, hv = t & 127, h = hv >> 4;
        const float* Vp = g_Vt + (b * 128 + hv) * Gn;
        const float* Lh = L + h * 200;
        u64 acc[QT];
        #pragma unroll
        for (int q = 0; q < QT; q++) acc[q] = 0ull;
        int gbeg = s * 50;
        for (int g = gbeg; g < gbeg + 50; g += 2) {
            u64 v2 = *(const u64*)(Vp + g);
            #pragma unroll
            for (int q = 0; q < QT; q++)
                acc[q] = fma2(*(const u64*)(Lh + q * 1600 + g), v2, acc[q]);
        }
        #pragma unroll
        for (int q = 0; q < QT; q++) hp[(s * 128 + hv) * QT + q] = hadd(acc[q]);
    }
    __syncthreads();
    if (t < 128) {
        #pragma unroll
        for (int q = 0; q < QT; q++) {
            float v = hp[t * QT + q] + hp[(128 + t) * QT + q]
                    + hp[(256 + t) * QT + q] + hp[(384 + t) * QT + q];
            headsd[q * 128 + t] = pk(v, v);
        }
    }
    __syncthreads();

    // ---- epilogue: out[q][e] = sum_hv heads[q][hv] * Wo[hv][e], e-pairs packed ----
    for (int u = t; u < 640; u += 512) {
        int q = u >> 6, e = (u & 63) * 2;
        u64 a = 0ull;
        const u64* hq = headsd + q * 128;
        #pragma unroll 16
        for (int hv = 0; hv < 128; hv++)
            a = fma2(hq[hv], *(const u64*)(Wo + hv * 128 + e), a);
        float2 r = up(a);
        *(float2*)(out + (size_t)(b * Gn + q0 + q) * 128 + e) = r;
    }
}

extern "C" void kernel_launch(void* const* d_in, const int* in_sizes, int n_in,
                              void* d_out, int out_size) {
    const float* h_em  = (const float*)d_in[0];
    const float* route = (const float*)d_in[1];
    const float* Wq    = (const float*)d_in[2];
    const float* Wk    = (const float*)d_in[3];
    const float* Wv    = (const float*)d_in[4];
    const float* W1    = (const float*)d_in[5];
    const float* b1    = (const float*)d_in[6];
    const float* W2    = (const float*)d_in[7];
    const float* b2    = (const float*)d_in[8];
    const float* Wo    = (const float*)d_in[9];
    float* out = (float*)d_out;

    // tuple output (out, route_attn) flattened: route passthrough after out
    float* out_route = nullptr;
    if (out_size >= 1638400 + 40960000) out_route = out + 1638400;

    static bool attr_done = false;
    if (!attr_done) {
        cudaFuncSetAttribute(qkv_kernel, cudaFuncAttributeMaxDynamicSharedMemorySize, SMEM1);
        cudaFuncSetAttribute(main_kernel, cudaFuncAttributeMaxDynamicSharedMemorySize, SMEM2);
        attr_done = true;
    }

    qkv_kernel<<<512, 256, SMEM1>>>(h_em, Wq, Wk, Wv);
    dim3 grid2(Gn / QT, Bn);
    main_kernel<<<grid2, 512, SMEM2>>>(route, W1, b1, W2, b2, Wo, out, out_route);
}

// round 3
// speedup vs baseline: 1.5816x; 1.5816x over previous
#include <cuda_runtime.h>
#include <cstdint>

typedef unsigned long long u64;

#define Bn 64
#define Gn 200
#define QT 10
#define LH 204                 // h-stride of L (204 mod 32 = 12 -> conflict-free)
#define LQ (8 * LH)            // 1632 q-stride

// ---------------- scratch (static device arrays; no allocation) ----------------
__device__ float g_Q[Bn * Gn * 128];          // [b][g][h*16+k]
__device__ float g_K[Bn * Gn * 128];          // [b][g][h*16+k]
__device__ float g_V[Bn * Gn * 128];          // [b][g][h*16+v]  (v-major, coalesced for AV)

// ---------------- packed f32x2 helpers ----------------
__device__ __forceinline__ u64 fma2(u64 a, u64 b, u64 c) {
    u64 d; asm("fma.rn.f32x2 %0, %1, %2, %3;" : "=l"(d) : "l"(a), "l"(b), "l"(c)); return d;
}
__device__ __forceinline__ u64 pk(float lo, float hi) {
    u64 d; asm("mov.b64 %0, {%1, %2};" : "=l"(d) : "f"(lo), "f"(hi)); return d;
}
__device__ __forceinline__ float2 up(u64 a) {
    float2 r; asm("mov.b64 {%0, %1}, %2;" : "=f"(r.x), "=f"(r.y) : "l"(a)); return r;
}
__device__ __forceinline__ float hadd(u64 a) { float2 r = up(a); return r.x + r.y; }

// ================= kernel 1: QKV projections (register-tiled GEMM) =================
// grid (4 gtiles of 50, 64 b, 3 wtype); 256 threads (16 tx x 16 ty); 2 CTAs/SM.
// Wsm[d][o] 16384 f + xs[d][gl] stride-65 8320 f = 98816 B.
#define SMEM1 ((16384 + 8320) * 4)

__global__ __launch_bounds__(256, 2) void proj_kernel(
    const float* __restrict__ h_em, const float* __restrict__ Wq,
    const float* __restrict__ Wk, const float* __restrict__ Wv)
{
    extern __shared__ float sm1[];
    float* Wsm = sm1;            // [d][o=h*16+k] : 128*128
    float* xs  = sm1 + 16384;    // [d][gl] stride 65

    int t  = threadIdx.x;
    int tx = t & 15, ty = t >> 4;
    int g0 = blockIdx.x * 50;
    int b  = blockIdx.y;
    int w  = blockIdx.z;
    const float* W = (w == 0) ? Wq : (w == 1) ? Wk : Wv;
    float* outp    = (w == 0) ? g_Q : (w == 1) ? g_K : g_V;

    // stage W[h][d][k] -> Wsm[d*128 + h*16 + k]
    for (int idx = t; idx < 16384; idx += 256) {
        int hh = idx >> 11, d = (idx >> 4) & 127, k = idx & 15;
        Wsm[d * 128 + hh * 16 + k] = W[idx];
    }
    // stage x transposed: xs[d][gl]
    const float4* xsrc = (const float4*)(h_em + (size_t)(b * Gn + g0) * 128);
    for (int i4 = t; i4 < 1600; i4 += 256) {
        float4 v = xsrc[i4];
        int gl = i4 >> 5, d4 = (i4 & 31) * 4;
        xs[(d4 + 0) * 65 + gl] = v.x;
        xs[(d4 + 1) * 65 + gl] = v.y;
        xs[(d4 + 2) * 65 + gl] = v.z;
        xs[(d4 + 3) * 65 + gl] = v.w;
    }
    __syncthreads();

    // thread tile: 4 g-rows (i*16+ty) x 8 outs (o = tx*2 + j*32), packed pairs
    u64 acc[4][4];
    #pragma unroll
    for (int i = 0; i < 4; i++)
        #pragma unroll
        for (int j = 0; j < 4; j++) acc[i][j] = 0ull;

    const u64* Wp = (const u64*)Wsm;
    #pragma unroll 2
    for (int d = 0; d < 128; d++) {
        u64 wv0 = Wp[d * 64 + tx];
        u64 wv1 = Wp[d * 64 + tx + 16];
        u64 wv2 = Wp[d * 64 + tx + 32];
        u64 wv3 = Wp[d * 64 + tx + 48];
        #pragma unroll
        for (int i = 0; i < 4; i++) {
            float x = xs[d * 65 + i * 16 + ty];
            u64 xv = pk(x, x);
            acc[i][0] = fma2(xv, wv0, acc[i][0]);
            acc[i][1] = fma2(xv, wv1, acc[i][1]);
            acc[i][2] = fma2(xv, wv2, acc[i][2]);
            acc[i][3] = fma2(xv, wv3, acc[i][3]);
        }
    }
    #pragma unroll
    for (int i = 0; i < 4; i++) {
        int gl = i * 16 + ty;
        if (gl < 50) {
            float* op = outp + (size_t)(b * Gn + g0 + gl) * 128 + tx * 2;
            #pragma unroll
            for (int j = 0; j < 4; j++) *(u64*)(op + j * 32) = acc[i][j];
        }
    }
}

// ================= kernel 2: fused qk + route + MLP + softmax + AV + Wout =================
// grid (20, 64); 768 threads; smem ~105 KB; 24 warps/SM.
#define SMEM2 ((16320 + 1280 + 5632) * 4 + (1280 + 384 + 128 + 16 + 8) * 8)

__global__ __launch_bounds__(768) void main_kernel(
    const float* __restrict__ route, const float* __restrict__ W1,
    const float* __restrict__ b1, const float* __restrict__ W2,
    const float* __restrict__ b2, const float* __restrict__ Wo,
    float* __restrict__ out, float* __restrict__ out_route)
{
    extern __shared__ char smraw[];
    float* L      = (float*)smraw;           // 16320 f : [q][h][g] strides LQ/LH
    float* Qsm    = L + 16320;               // 1280 f  : [q][chunk-swizzled 128]
    float* hp     = Qsm + 1280;              // 5632 f  : [s(4)][hv][11]
    u64*   headsd = (u64*)(hp + 5632);       // 1280 u64: [q][hv] duplicated pairs
    u64*   W1d    = headsd + 1280;           // 384
    u64*   W2d    = W1d + 384;               // 128
    u64*   b1d    = W2d + 128;               // 16
    u64*   b2d    = b1d + 16;                // 8

    int t  = threadIdx.x;
    int b  = blockIdx.y;
    int q0 = blockIdx.x * QT;

    // ---- phase 0: stage Q (chunk-permuted), dup weight tables ----
    const float4* Qs = (const float4*)(g_Q + (size_t)(b * Gn + q0) * 128);
    for (int i4 = t; i4 < 320; i4 += 768) {
        float4 v = Qs[i4];
        int q = i4 >> 5, rem = i4 & 31, h = rem >> 2, c = rem & 3;
        int chunk = h * 4 + ((c + (h >> 1)) & 3);
        *(float4*)(Qsm + q * 128 + chunk * 4) = v;
    }
    if (t < 384) W1d[t] = pk(W1[t], W1[t]);
    if (t >= 384 && t < 512) { int i = t - 384; W2d[i] = pk(W2[i], W2[i]); }
    if (t >= 512 && t < 528) { int i = t - 512; b1d[i] = pk(b1[i], b1[i]); }
    if (t >= 528 && t < 536) { int i = t - 528; b2d[i] = pk(b2[i], b2[i]); }
    __syncthreads();

    // ---- phase 1a: raw qk -> L.  item (g,h), g-major for coalesced K LDG ----
    for (int u = t; u < 1600; u += 768) {
        int g = u >> 3, h = u & 7;
        const u64* Kp = (const u64*)(g_K + (size_t)(b * Gn + g) * 128 + h * 16);
        u64 kv[8];
        #pragma unroll
        for (int i = 0; i < 8; i++) kv[i] = Kp[i];
        int h2 = h >> 1;
        float* Ld = L + h * LH + g;
        #pragma unroll
        for (int q = 0; q < QT; q++) {
            const float* Qr = Qsm + q * 128;
            u64 a = 0ull;
            #pragma unroll
            for (int c = 0; c < 4; c++) {
                int p = h * 4 + ((c + h2) & 3);
                ulonglong2 qc = *(const ulonglong2*)(Qr + p * 4);
                a = fma2(kv[2 * c], qc.x, a);
                a = fma2(kv[2 * c + 1], qc.y, a);
            }
            Ld[q * LQ] = hadd(a);
        }
    }
    __syncthreads();

    // ---- phase 1b: per (q, g-pair): stream 24 inputs through hid[16], route passthrough ----
    for (int u = t; u < 1000; u += 768) {
        int q  = u / 100;
        int gp = u - q * 100;
        int g  = gp * 2;
        u64 hid[16];
        #pragma unroll
        for (int j = 0; j < 16; j++) hid[j] = b1d[j];
        float* Lqg = L + q * LQ + g;
        #pragma unroll
        for (int h = 0; h < 8; h++) {
            u64 x = *(const u64*)(Lqg + h * LH);
            #pragma unroll
            for (int j = 0; j < 16; j++) hid[j] = fma2(x, W1d[j * 24 + h], hid[j]);
        }
        size_t ridx = (size_t)(b * Gn + q0 + q) * Gn + g;
        const float* rp = route + ridx;
        float* wp = out_route ? (out_route + ridx) : (float*)0;
        #pragma unroll
        for (int r0 = 0; r0 < 16; r0 += 4) {
            u64 rv0 = *(const u64*)(rp + (size_t)(r0 + 0) * 2560000);
            u64 rv1 = *(const u64*)(rp + (size_t)(r0 + 1) * 2560000);
            u64 rv2 = *(const u64*)(rp + (size_t)(r0 + 2) * 2560000);
            u64 rv3 = *(const u64*)(rp + (size_t)(r0 + 3) * 2560000);
            if (wp) {
                *(u64*)(wp + (size_t)(r0 + 0) * 2560000) = rv0;
                *(u64*)(wp + (size_t)(r0 + 1) * 2560000) = rv1;
                *(u64*)(wp + (size_t)(r0 + 2) * 2560000) = rv2;
                *(u64*)(wp + (size_t)(r0 + 3) * 2560000) = rv3;
            }
            #pragma unroll
            for (int j = 0; j < 16; j++) {
                hid[j] = fma2(rv0, W1d[j * 24 + 8 + r0], hid[j]);
                hid[j] = fma2(rv1, W1d[j * 24 + 9 + r0], hid[j]);
                hid[j] = fma2(rv2, W1d[j * 24 + 10 + r0], hid[j]);
                hid[j] = fma2(rv3, W1d[j * 24 + 11 + r0], hid[j]);
            }
        }
        #pragma unroll
        for (int j = 0; j < 16; j++) {
            float2 v = up(hid[j]);
            hid[j] = pk(fmaxf(v.x, 0.f), fmaxf(v.y, 0.f));
        }
        #pragma unroll
        for (int h = 0; h < 8; h++) {
            u64 a = b2d[h];
            #pragma unroll
            for (int j = 0; j < 16; j++) a = fma2(hid[j], W2d[h * 16 + j], a);
            *(u64*)(Lqg + h * LH) = a;
        }
    }
    __syncthreads();

    // ---- phase 2: softmax over g, one warp per (q,h) row ----
    {
        int warp = t >> 5, lane = t & 31;
        for (int row = warp; row < 80; row += 24) {
            float* Lr = L + (row >> 3) * LQ + (row & 7) * LH;
            float m = -1e30f;
            for (int i = lane; i < 200; i += 32) m = fmaxf(m, Lr[i]);
            #pragma unroll
            for (int o = 16; o > 0; o >>= 1) m = fmaxf(m, __shfl_xor_sync(0xffffffffu, m, o));
            float s = 0.f;
            for (int i = lane; i < 200; i += 32) { float e = __expf(Lr[i] - m); Lr[i] = e; s += e; }
            #pragma unroll
            for (int o = 16; o > 0; o >>= 1) s += __shfl_xor_sync(0xffffffffu, s, o);
            float inv = 1.f / s;
            for (int i = lane; i < 200; i += 32) Lr[i] *= inv;
        }
    }
    __syncthreads();

    // ---- phase 3: heads[q][hv] = sum_g p[q][h][g] * V[g][hv] (coalesced v, q-pair packed) ----
    if (t < 512) {
        int s = t >> 7, hv = t & 127, h = hv >> 4;
        const float* Vp = g_V + (size_t)(b * Gn + s * 50) * 128 + hv;
        const float* Lh = L + h * LH + s * 50;
        u64 acc[5];
        #pragma unroll
        for (int qp = 0; qp < 5; qp++) acc[qp] = 0ull;
        for (int i = 0; i < 50; i++) {
            float v = Vp[i * 128];
            u64 v2 = pk(v, v);
            #pragma unroll
            for (int qp = 0; qp < 5; qp++) {
                u64 p2 = pk(Lh[(2 * qp) * LQ + i], Lh[(2 * qp + 1) * LQ + i]);
                acc[qp] = fma2(p2, v2, acc[qp]);
            }
        }
        float* hpd = hp + (s * 128 + hv) * 11;
        #pragma unroll
        for (int qp = 0; qp < 5; qp++) {
            float2 r = up(acc[qp]);
            hpd[2 * qp] = r.x; hpd[2 * qp + 1] = r.y;
        }
    }
    __syncthreads();
    if (t < 128) {
        #pragma unroll
        for (int q = 0; q < QT; q++) {
            float v = hp[t * 11 + q] + hp[(128 + t) * 11 + q]
                    + hp[(256 + t) * 11 + q] + hp[(384 + t) * 11 + q];
            headsd[q * 128 + t] = pk(v, v);
        }
    }
    __syncthreads();

    // ---- epilogue: out[q][e] = sum_hv heads[q][hv] * Wo[hv][e], e-pairs packed ----
    for (int u = t; u < 640; u += 768) {
        int q = u >> 6, e2 = u & 63;
        u64 a = 0ull;
        const u64* hq = headsd + q * 128;
        const u64* Wop = (const u64*)Wo + e2;
        #pragma unroll 16
        for (int hv = 0; hv < 128; hv++)
            a = fma2(hq[hv], Wop[hv * 64], a);
        float2 r = up(a);
        *(float2*)(out + (size_t)(b * Gn + q0 + q) * 128 + e2 * 2) = r;
    }
}

extern "C" void kernel_launch(void* const* d_in, const int* in_sizes, int n_in,
                              void* d_out, int out_size) {
    const float* h_em  = (const float*)d_in[0];
    const float* route = (const float*)d_in[1];
    const float* Wq    = (const float*)d_in[2];
    const float* Wk    = (const float*)d_in[3];
    const float* Wv    = (const float*)d_in[4];
    const float* W1    = (const float*)d_in[5];
    const float* b1    = (const float*)d_in[6];
    const float* W2    = (const float*)d_in[7];
    const float* b2    = (const float*)d_in[8];
    const float* Wo    = (const float*)d_in[9];
    float* out = (float*)d_out;

    // tuple output (out, route_attn) flattened: route passthrough after out
    float* out_route = nullptr;
    if (out_size >= 1638400 + 40960000) out_route = out + 1638400;

    static bool attr_done = false;
    if (!attr_done) {
        cudaFuncSetAttribute(proj_kernel, cudaFuncAttributeMaxDynamicSharedMemorySize, SMEM1);
        cudaFuncSetAttribute(main_kernel, cudaFuncAttributeMaxDynamicSharedMemorySize, SMEM2);
        attr_done = true;
    }

    dim3 grid1(4, Bn, 3);
    proj_kernel<<<grid1, 256, SMEM1>>>(h_em, Wq, Wk, Wv);
    dim3 grid2(Gn / QT, Bn);
    main_kernel<<<grid2, 768, SMEM2>>>(route, W1, b1, W2, b2, Wo, out, out_route);
}

// round 4
// speedup vs baseline: 1.8217x; 1.1518x over previous
#include <cuda_runtime.h>
#include <cstdint>

typedef unsigned long long u64;

#define Bn 64
#define Gn 200
#define QT 5
#define LH 204                 // h-stride of L (204 mod 32 = 12 -> conflict-free)
#define LQ (8 * LH)            // 1632 q-stride

// ---------------- scratch (static device arrays; no allocation) ----------------
__device__ float g_Q[Bn * Gn * 128];          // [b][g][h*16+k]
__device__ float g_K[Bn * Gn * 128];          // [b][g][h*16+k]
__device__ float g_V[Bn * Gn * 128];          // [b][g][h*16+v]  (v-major, coalesced for AV)

// ---------------- packed f32x2 helpers ----------------
__device__ __forceinline__ u64 fma2(u64 a, u64 b, u64 c) {
    u64 d; asm("fma.rn.f32x2 %0, %1, %2, %3;" : "=l"(d) : "l"(a), "l"(b), "l"(c)); return d;
}
__device__ __forceinline__ u64 pk(float lo, float hi) {
    u64 d; asm("mov.b64 %0, {%1, %2};" : "=l"(d) : "f"(lo), "f"(hi)); return d;
}
__device__ __forceinline__ float2 up(u64 a) {
    float2 r; asm("mov.b64 {%0, %1}, %2;" : "=f"(r.x), "=f"(r.y) : "l"(a)); return r;
}
__device__ __forceinline__ float hadd(u64 a) { float2 r = up(a); return r.x + r.y; }

// ================= kernel 1: QKV projections (register-tiled, o-split for 3 CTAs/SM) =================
// grid (4 gtiles of 50, 64 b, 3 wtype); 256 threads (16 tx x 16 ty).
// smem: Wsm[d][64] 8192 f + xs[d][gl] stride-65 8320 f = 66 KB -> 3 CTAs/SM.
#define SMEM1 ((8192 + 8320) * 4)

__global__ __launch_bounds__(256, 3) void proj_kernel(
    const float* __restrict__ h_em, const float* __restrict__ Wq,
    const float* __restrict__ Wk, const float* __restrict__ Wv)
{
    extern __shared__ float sm1[];
    float* Wsm = sm1;            // [d][o_local 64]
    float* xs  = sm1 + 8192;     // [d][gl] stride 65

    int t  = threadIdx.x;
    int tx = t & 15, ty = t >> 4;
    int g0 = blockIdx.x * 50;
    int b  = blockIdx.y;
    int w  = blockIdx.z;
    const float* W = (w == 0) ? Wq : (w == 1) ? Wk : Wv;
    float* outp    = (w == 0) ? g_Q : (w == 1) ? g_K : g_V;

    // stage x transposed: xs[d][gl]
    const float4* xsrc = (const float4*)(h_em + (size_t)(b * Gn + g0) * 128);
    for (int i4 = t; i4 < 1600; i4 += 256) {
        float4 v = xsrc[i4];
        int gl = i4 >> 5, d4 = (i4 & 31) * 4;
        xs[(d4 + 0) * 65 + gl] = v.x;
        xs[(d4 + 1) * 65 + gl] = v.y;
        xs[(d4 + 2) * 65 + gl] = v.z;
        xs[(d4 + 3) * 65 + gl] = v.w;
    }

    #pragma unroll 1
    for (int wh = 0; wh < 2; wh++) {
        if (wh) __syncthreads();
        // stage W[h][d][k] half -> Wsm[d*64 + hl*16 + k], h = wh*4 + hl
        for (int idx = t; idx < 8192; idx += 256) {
            int hl = idx >> 11, d = (idx >> 4) & 127, k = idx & 15;
            Wsm[d * 64 + hl * 16 + k] = W[(wh * 4 + hl) * 2048 + d * 16 + k];
        }
        __syncthreads();

        u64 acc[4][2];
        #pragma unroll
        for (int i = 0; i < 4; i++) { acc[i][0] = 0ull; acc[i][1] = 0ull; }

        const u64* Wp = (const u64*)Wsm;
        #pragma unroll 4
        for (int d = 0; d < 128; d++) {
            u64 wv0 = Wp[d * 32 + tx];
            u64 wv1 = Wp[d * 32 + tx + 16];
            #pragma unroll
            for (int i = 0; i < 4; i++) {
                float x = xs[d * 65 + i * 16 + ty];
                u64 xv = pk(x, x);
                acc[i][0] = fma2(xv, wv0, acc[i][0]);
                acc[i][1] = fma2(xv, wv1, acc[i][1]);
            }
        }
        #pragma unroll
        for (int i = 0; i < 4; i++) {
            int gl = i * 16 + ty;
            if (gl < 50) {
                float* op = outp + (size_t)(b * Gn + g0 + gl) * 128 + wh * 64 + tx * 2;
                *(u64*)op        = acc[i][0];
                *(u64*)(op + 32) = acc[i][1];
            }
        }
    }
}

// ================= kernel 2: fused qk + route + MLP + softmax + AV + Wout =================
// grid (40, 64); 512 threads; smem ~58 KB; 2 CTAs/SM -> 32 warps.
#define SMEM2 ((8160 + 640 + 3584) * 4 + (640 + 384 + 128 + 16 + 8) * 8)

__global__ __launch_bounds__(512, 2) void main_kernel(
    const float* __restrict__ route, const float* __restrict__ W1,
    const float* __restrict__ b1, const float* __restrict__ W2,
    const float* __restrict__ b2, const float* __restrict__ Wo,
    float* __restrict__ out, float* __restrict__ out_route)
{
    extern __shared__ char smraw[];
    float* L      = (float*)smraw;           // 8160 f : [q][h][g] strides LQ/LH
    float* Qsm    = L + 8160;                // 640 f  : [q][chunk-swizzled 128]
    float* hp     = Qsm + 640;               // 3584 f : [s(4)][hv][7]
    u64*   headsd = (u64*)(hp + 3584);       // 640 u64: [q][hv] duplicated pairs
    u64*   W1d    = headsd + 640;            // 384
    u64*   W2d    = W1d + 384;               // 128
    u64*   b1d    = W2d + 128;               // 16
    u64*   b2d    = b1d + 16;                // 8

    int t  = threadIdx.x;
    int b  = blockIdx.y;
    int q0 = blockIdx.x * QT;

    // ---- phase 0: stage Q (chunk-permuted), dup weight tables ----
    const float4* Qs = (const float4*)(g_Q + (size_t)(b * Gn + q0) * 128);
    for (int i4 = t; i4 < 160; i4 += 512) {
        float4 v = Qs[i4];
        int q = i4 >> 5, rem = i4 & 31, h = rem >> 2, c = rem & 3;
        int chunk = h * 4 + ((c + (h >> 1)) & 3);
        *(float4*)(Qsm + q * 128 + chunk * 4) = v;
    }
    if (t < 384) W1d[t] = pk(W1[t], W1[t]);
    if (t >= 384 && t < 512) { int i = t - 384; W2d[i] = pk(W2[i], W2[i]); }
    if (t < 16)  { b1d[t] = pk(b1[t], b1[t]); }
    if (t >= 16 && t < 24) { int i = t - 16; b2d[i] = pk(b2[i], b2[i]); }
    __syncthreads();

    // ---- phase 1a: raw qk -> L.  item (g,h), h fastest so a warp covers full K rows ----
    for (int u = t; u < 1600; u += 512) {
        int g = u >> 3, h = u & 7;
        const ulonglong2* Kp = (const ulonglong2*)(g_K + (size_t)(b * Gn + g) * 128 + h * 16);
        ulonglong2 kv[4];
        #pragma unroll
        for (int i = 0; i < 4; i++) kv[i] = Kp[i];
        int h2 = h >> 1;
        float* Ld = L + h * LH + g;
        #pragma unroll
        for (int q = 0; q < QT; q++) {
            const float* Qr = Qsm + q * 128;
            u64 a = 0ull;
            #pragma unroll
            for (int c = 0; c < 4; c++) {
                int p = h * 4 + ((c + h2) & 3);
                ulonglong2 qc = *(const ulonglong2*)(Qr + p * 4);
                a = fma2(kv[c].x, qc.x, a);
                a = fma2(kv[c].y, qc.y, a);
            }
            Ld[q * LQ] = hadd(a);
        }
    }
    __syncthreads();

    // ---- phase 1b: per (q, g-pair): stream 24 inputs through hid[16], route passthrough ----
    if (t < 500) {
        int q  = t / 100;
        int gp = t - q * 100;
        int g  = gp * 2;
        u64 hid[16];
        #pragma unroll
        for (int j = 0; j < 16; j++) hid[j] = b1d[j];
        float* Lqg = L + q * LQ + g;
        #pragma unroll
        for (int h = 0; h < 8; h++) {
            u64 x = *(const u64*)(Lqg + h * LH);
            #pragma unroll
            for (int j = 0; j < 16; j++) hid[j] = fma2(x, W1d[j * 24 + h], hid[j]);
        }
        size_t ridx = (size_t)(b * Gn + q0 + q) * Gn + g;
        const u64* rp = (const u64*)(route + ridx);
        u64* wp = out_route ? (u64*)(out_route + ridx) : (u64*)0;
        #pragma unroll
        for (int r0 = 0; r0 < 16; r0 += 4) {
            u64 rv0 = __ldcs(rp + (size_t)(r0 + 0) * 1280000);
            u64 rv1 = __ldcs(rp + (size_t)(r0 + 1) * 1280000);
            u64 rv2 = __ldcs(rp + (size_t)(r0 + 2) * 1280000);
            u64 rv3 = __ldcs(rp + (size_t)(r0 + 3) * 1280000);
            if (wp) {
                __stcs(wp + (size_t)(r0 + 0) * 1280000, rv0);
                __stcs(wp + (size_t)(r0 + 1) * 1280000, rv1);
                __stcs(wp + (size_t)(r0 + 2) * 1280000, rv2);
                __stcs(wp + (size_t)(r0 + 3) * 1280000, rv3);
            }
            #pragma unroll
            for (int j = 0; j < 16; j++) {
                hid[j] = fma2(rv0, W1d[j * 24 + 8 + r0], hid[j]);
                hid[j] = fma2(rv1, W1d[j * 24 + 9 + r0], hid[j]);
                hid[j] = fma2(rv2, W1d[j * 24 + 10 + r0], hid[j]);
                hid[j] = fma2(rv3, W1d[j * 24 + 11 + r0], hid[j]);
            }
        }
        #pragma unroll
        for (int j = 0; j < 16; j++) {
            float2 v = up(hid[j]);
            hid[j] = pk(fmaxf(v.x, 0.f), fmaxf(v.y, 0.f));
        }
        #pragma unroll
        for (int h = 0; h < 8; h++) {
            u64 a = b2d[h];
            #pragma unroll
            for (int j = 0; j < 16; j++) a = fma2(hid[j], W2d[h * 16 + j], a);
            *(u64*)(Lqg + h * LH) = a;
        }
    }
    __syncthreads();

    // ---- phase 2: softmax over g, one warp per (q,h) row ----
    {
        int warp = t >> 5, lane = t & 31;
        for (int row = warp; row < 40; row += 16) {
            float* Lr = L + (row >> 3) * LQ + (row & 7) * LH;
            float m = -1e30f;
            for (int i = lane; i < 200; i += 32) m = fmaxf(m, Lr[i]);
            #pragma unroll
            for (int o = 16; o > 0; o >>= 1) m = fmaxf(m, __shfl_xor_sync(0xffffffffu, m, o));
            float s = 0.f;
            for (int i = lane; i < 200; i += 32) { float e = __expf(Lr[i] - m); Lr[i] = e; s += e; }
            #pragma unroll
            for (int o = 16; o > 0; o >>= 1) s += __shfl_xor_sync(0xffffffffu, s, o);
            float inv = 1.f / s;
            for (int i = lane; i < 200; i += 32) Lr[i] *= inv;
        }
    }
    __syncthreads();

    // ---- phase 3: heads[q][hv] = sum_g p[q][h][g] * V[g][hv] (coalesced v) ----
    {
        int s = t >> 7, hv = t & 127, h = hv >> 4;
        const float* Vp = g_V + (size_t)(b * Gn + s * 50) * 128 + hv;
        const float* Lh = L + h * LH + s * 50;
        u64 acc01 = 0ull, acc23 = 0ull;
        float acc4 = 0.f;
        for (int i = 0; i < 50; i++) {
            float v = Vp[i * 128];
            u64 v2 = pk(v, v);
            acc01 = fma2(pk(Lh[0 * LQ + i], Lh[1 * LQ + i]), v2, acc01);
            acc23 = fma2(pk(Lh[2 * LQ + i], Lh[3 * LQ + i]), v2, acc23);
            acc4 = fmaf(Lh[4 * LQ + i], v, acc4);
        }
        float* hpd = hp + (s * 128 + hv) * 7;
        float2 r01 = up(acc01), r23 = up(acc23);
        hpd[0] = r01.x; hpd[1] = r01.y;
        hpd[2] = r23.x; hpd[3] = r23.y;
        hpd[4] = acc4;
    }
    __syncthreads();
    if (t < 128) {
        #pragma unroll
        for (int q = 0; q < QT; q++) {
            float v = hp[t * 7 + q] + hp[(128 + t) * 7 + q]
                    + hp[(256 + t) * 7 + q] + hp[(384 + t) * 7 + q];
            headsd[q * 128 + t] = pk(v, v);
        }
    }
    __syncthreads();

    // ---- epilogue: out[q][e] = sum_hv heads[q][hv] * Wo[hv][e], e-pairs packed ----
    if (t < 320) {
        int q = t >> 6, e2 = t & 63;
        u64 a = 0ull;
        const u64* hq = headsd + q * 128;
        const u64* Wop = (const u64*)Wo + e2;
        #pragma unroll 16
        for (int hv = 0; hv < 128; hv++)
            a = fma2(hq[hv], Wop[hv * 64], a);
        float2 r = up(a);
        *(float2*)(out + (size_t)(b * Gn + q0 + q) * 128 + e2 * 2) = r;
    }
}

extern "C" void kernel_launch(void* const* d_in, const int* in_sizes, int n_in,
                              void* d_out, int out_size) {
    const float* h_em  = (const float*)d_in[0];
    const float* route = (const float*)d_in[1];
    const float* Wq    = (const float*)d_in[2];
    const float* Wk    = (const float*)d_in[3];
    const float* Wv    = (const float*)d_in[4];
    const float* W1    = (const float*)d_in[5];
    const float* b1    = (const float*)d_in[6];
    const float* W2    = (const float*)d_in[7];
    const float* b2    = (const float*)d_in[8];
    const float* Wo    = (const float*)d_in[9];
    float* out = (float*)d_out;

    // tuple output (out, route_attn) flattened: route passthrough after out
    float* out_route = nullptr;
    if (out_size >= 1638400 + 40960000) out_route = out + 1638400;

    static bool attr_done = false;
    if (!attr_done) {
        cudaFuncSetAttribute(proj_kernel, cudaFuncAttributeMaxDynamicSharedMemorySize, SMEM1);
        cudaFuncSetAttribute(main_kernel, cudaFuncAttributeMaxDynamicSharedMemorySize, SMEM2);
        attr_done = true;
    }

    dim3 grid1(4, Bn, 3);
    proj_kernel<<<grid1, 256, SMEM1>>>(h_em, Wq, Wk, Wv);
    dim3 grid2(Gn / QT, Bn);
    main_kernel<<<grid2, 512, SMEM2>>>(route, W1, b1, W2, b2, Wo, out, out_route);
}

// round 5
// speedup vs baseline: 1.9804x; 1.0871x over previous
#include <cuda_runtime.h>
#include <cstdint>

typedef unsigned long long u64;

#define Bn 64
#define Gn 200
#define QT 10
#define LH 204                 // h-stride of L (204 mod 32 = 12 -> conflict-free)
#define LQ (8 * LH)            // 1632 q-stride

// ---------------- scratch (static device arrays; no allocation) ----------------
__device__ float g_Q[Bn * Gn * 128];          // [b][g][h*16+k]
__device__ float g_K[Bn * Gn * 128];          // [b][g][h*16+k]
__device__ float g_V[Bn * Gn * 128];          // [b][g][h*16+v]  (v-major, coalesced for AV)

// ---------------- packed f32x2 helpers ----------------
__device__ __forceinline__ u64 fma2(u64 a, u64 b, u64 c) {
    u64 d; asm("fma.rn.f32x2 %0, %1, %2, %3;" : "=l"(d) : "l"(a), "l"(b), "l"(c)); return d;
}
__device__ __forceinline__ u64 pk(float lo, float hi) {
    u64 d; asm("mov.b64 %0, {%1, %2};" : "=l"(d) : "f"(lo), "f"(hi)); return d;
}
__device__ __forceinline__ float2 up(u64 a) {
    float2 r; asm("mov.b64 {%0, %1}, %2;" : "=f"(r.x), "=f"(r.y) : "l"(a)); return r;
}
__device__ __forceinline__ float hadd(u64 a) { float2 r = up(a); return r.x + r.y; }

// ================= kernel 1: QKV projections (register-tiled, o-split for 3 CTAs/SM) =================
#define SMEM1 ((8192 + 8320) * 4)

__global__ __launch_bounds__(256, 3) void proj_kernel(
    const float* __restrict__ h_em, const float* __restrict__ Wq,
    const float* __restrict__ Wk, const float* __restrict__ Wv)
{
    extern __shared__ float sm1[];
    float* Wsm = sm1;            // [d][o_local 64]
    float* xs  = sm1 + 8192;     // [d][gl] stride 65

    int t  = threadIdx.x;
    int tx = t & 15, ty = t >> 4;
    int g0 = blockIdx.x * 50;
    int b  = blockIdx.y;
    int w  = blockIdx.z;
    const float* W = (w == 0) ? Wq : (w == 1) ? Wk : Wv;
    float* outp    = (w == 0) ? g_Q : (w == 1) ? g_K : g_V;

    const float4* xsrc = (const float4*)(h_em + (size_t)(b * Gn + g0) * 128);
    for (int i4 = t; i4 < 1600; i4 += 256) {
        float4 v = xsrc[i4];
        int gl = i4 >> 5, d4 = (i4 & 31) * 4;
        xs[(d4 + 0) * 65 + gl] = v.x;
        xs[(d4 + 1) * 65 + gl] = v.y;
        xs[(d4 + 2) * 65 + gl] = v.z;
        xs[(d4 + 3) * 65 + gl] = v.w;
    }

    #pragma unroll 1
    for (int wh = 0; wh < 2; wh++) {
        if (wh) __syncthreads();
        for (int idx = t; idx < 8192; idx += 256) {
            int hl = idx >> 11, d = (idx >> 4) & 127, k = idx & 15;
            Wsm[d * 64 + hl * 16 + k] = W[(wh * 4 + hl) * 2048 + d * 16 + k];
        }
        __syncthreads();

        u64 acc[4][2];
        #pragma unroll
        for (int i = 0; i < 4; i++) { acc[i][0] = 0ull; acc[i][1] = 0ull; }

        const u64* Wp = (const u64*)Wsm;
        #pragma unroll 4
        for (int d = 0; d < 128; d++) {
            u64 wv0 = Wp[d * 32 + tx];
            u64 wv1 = Wp[d * 32 + tx + 16];
            #pragma unroll
            for (int i = 0; i < 4; i++) {
                float x = xs[d * 65 + i * 16 + ty];
                u64 xv = pk(x, x);
                acc[i][0] = fma2(xv, wv0, acc[i][0]);
                acc[i][1] = fma2(xv, wv1, acc[i][1]);
            }
        }
        #pragma unroll
        for (int i = 0; i < 4; i++) {
            int gl = i * 16 + ty;
            if (gl < 50) {
                float* op = outp + (size_t)(b * Gn + g0 + gl) * 128 + wh * 64 + tx * 2;
                *(u64*)op        = acc[i][0];
                *(u64*)(op + 32) = acc[i][1];
            }
        }
    }
}

// ================= kernel 2: fused qk + route + MLP + softmax + AV + Wout =================
// grid (20, 64); 512 threads; smem ~105 KB; 2 CTAs/SM -> 32 warps.
#define SMEM2 ((16320 + 1280 + 5632) * 4 + (1280 + 384 + 128 + 16 + 8) * 8)

__global__ __launch_bounds__(512, 2) void main_kernel(
    const float* __restrict__ route, const float* __restrict__ W1,
    const float* __restrict__ b1, const float* __restrict__ W2,
    const float* __restrict__ b2, const float* __restrict__ Wo,
    float* __restrict__ out, float* __restrict__ out_route)
{
    extern __shared__ char smraw[];
    float* L      = (float*)smraw;           // 16320 f : [q][h][g] strides LQ/LH
    float* Qsm    = L + 16320;               // 1280 f  : [q][chunk-swizzled 128]
    float* hp     = Qsm + 1280;              // 5632 f  : [s(4)][hv][11]  (reused as epilogue scratch)
    u64*   headsd = (u64*)(hp + 5632);       // 1280 u64: [q][hv] duplicated pairs
    u64*   W1d    = headsd + 1280;           // 384
    u64*   W2d    = W1d + 384;               // 128
    u64*   b1d    = W2d + 128;               // 16
    u64*   b2d    = b1d + 16;                // 8

    int t  = threadIdx.x;
    int b  = blockIdx.y;
    int q0 = blockIdx.x * QT;

    // ---- phase 0: stage Q (chunk-permuted), dup weight tables ----
    const float4* Qs = (const float4*)(g_Q + (size_t)(b * Gn + q0) * 128);
    for (int i4 = t; i4 < 320; i4 += 512) {
        float4 v = Qs[i4];
        int q = i4 >> 5, rem = i4 & 31, h = rem >> 2, c = rem & 3;
        int chunk = h * 4 + ((c + (h >> 1)) & 3);
        *(float4*)(Qsm + q * 128 + chunk * 4) = v;
    }
    if (t < 384) W1d[t] = pk(W1[t], W1[t]);
    if (t >= 384 && t < 512) { int i = t - 384; W2d[i] = pk(W2[i], W2[i]); }
    if (t < 16)  { b1d[t] = pk(b1[t], b1[t]); }
    if (t >= 16 && t < 24) { int i = t - 16; b2d[i] = pk(b2[i], b2[i]); }
    __syncthreads();

    // ---- phase 1a: raw qk -> L.  item (g,h), h fastest ----
    for (int u = t; u < 1600; u += 512) {
        int g = u >> 3, h = u & 7;
        const ulonglong2* Kp = (const ulonglong2*)(g_K + (size_t)(b * Gn + g) * 128 + h * 16);
        ulonglong2 kv[4];
        #pragma unroll
        for (int i = 0; i < 4; i++) kv[i] = Kp[i];
        int h2 = h >> 1;
        float* Ld = L + h * LH + g;
        #pragma unroll
        for (int q = 0; q < QT; q++) {
            const float* Qr = Qsm + q * 128;
            u64 a = 0ull;
            #pragma unroll
            for (int c = 0; c < 4; c++) {
                int p = h * 4 + ((c + h2) & 3);
                ulonglong2 qc = *(const ulonglong2*)(Qr + p * 4);
                a = fma2(kv[c].x, qc.x, a);
                a = fma2(kv[c].y, qc.y, a);
            }
            Ld[q * LQ] = hadd(a);
        }
    }
    __syncthreads();

    // ---- phase 1b: per (q, g-pair): stream 24 inputs through hid[16]; weights via LDS.128 pairs ----
    const ulonglong2* W1p = (const ulonglong2*)W1d;
    const ulonglong2* W2p = (const ulonglong2*)W2d;
    for (int u = t; u < 1000; u += 512) {
        int q  = u / 100;
        int gp = u - q * 100;
        int g  = gp * 2;
        u64 hid[16];
        #pragma unroll
        for (int j = 0; j < 16; j++) hid[j] = b1d[j];
        float* Lqg = L + q * LQ + g;
        #pragma unroll
        for (int h = 0; h < 8; h += 2) {
            u64 x0 = *(const u64*)(Lqg + h * LH);
            u64 x1 = *(const u64*)(Lqg + (h + 1) * LH);
            #pragma unroll
            for (int j = 0; j < 16; j++) {
                ulonglong2 w = W1p[j * 12 + (h >> 1)];
                hid[j] = fma2(x0, w.x, hid[j]);
                hid[j] = fma2(x1, w.y, hid[j]);
            }
        }
        size_t ridx = (size_t)(b * Gn + q0 + q) * Gn + g;
        const u64* rp = (const u64*)(route + ridx);
        u64* wp = out_route ? (u64*)(out_route + ridx) : (u64*)0;
        #pragma unroll
        for (int r0 = 0; r0 < 16; r0 += 2) {
            u64 rv0 = __ldcs(rp + (size_t)(r0 + 0) * 1280000);
            u64 rv1 = __ldcs(rp + (size_t)(r0 + 1) * 1280000);
            if (wp) {
                __stcs(wp + (size_t)(r0 + 0) * 1280000, rv0);
                __stcs(wp + (size_t)(r0 + 1) * 1280000, rv1);
            }
            #pragma unroll
            for (int j = 0; j < 16; j++) {
                ulonglong2 w = W1p[j * 12 + 4 + (r0 >> 1)];
                hid[j] = fma2(rv0, w.x, hid[j]);
                hid[j] = fma2(rv1, w.y, hid[j]);
            }
        }
        #pragma unroll
        for (int j = 0; j < 16; j++) {
            float2 v = up(hid[j]);
            hid[j] = pk(fmaxf(v.x, 0.f), fmaxf(v.y, 0.f));
        }
        #pragma unroll
        for (int h = 0; h < 8; h++) {
            u64 a = b2d[h];
            #pragma unroll
            for (int j = 0; j < 16; j += 2) {
                ulonglong2 w = W2p[(h * 16 + j) >> 1];
                a = fma2(hid[j], w.x, a);
                a = fma2(hid[j + 1], w.y, a);
            }
            *(u64*)(Lqg + h * LH) = a;
        }
    }
    __syncthreads();

    // ---- phase 2: softmax over g, one warp per (q,h) row; 80 rows / 16 warps = 5 rounds ----
    {
        int warp = t >> 5, lane = t & 31;
        for (int row = warp; row < 80; row += 16) {
            float* Lr = L + (row >> 3) * LQ + (row & 7) * LH;
            float m = -1e30f;
            for (int i = lane; i < 200; i += 32) m = fmaxf(m, Lr[i]);
            #pragma unroll
            for (int o = 16; o > 0; o >>= 1) m = fmaxf(m, __shfl_xor_sync(0xffffffffu, m, o));
            float s = 0.f;
            for (int i = lane; i < 200; i += 32) { float e = __expf(Lr[i] - m); Lr[i] = e; s += e; }
            #pragma unroll
            for (int o = 16; o > 0; o >>= 1) s += __shfl_xor_sync(0xffffffffu, s, o);
            float inv = 1.f / s;
            for (int i = lane; i < 200; i += 32) Lr[i] *= inv;
        }
    }
    __syncthreads();

    // ---- phase 3: heads[q][hv] = sum_g p[q][h][g] * V[g][hv]; g-quads, aligned slices {52,52,48,48} ----
    {
        int s = t >> 7, hv = t & 127, h = hv >> 4;
        int base = s * 48 + ((s < 2) ? s * 4 : 8);   // 0, 52, 104, 152
        int len  = (s < 2) ? 52 : 48;
        const float* Vp = g_V + (size_t)(b * Gn + base) * 128 + hv;
        const float* Lh = L + h * LH + base;
        u64 acc[QT];
        #pragma unroll
        for (int q = 0; q < QT; q++) acc[q] = 0ull;
        for (int i = 0; i < len; i += 4) {
            float v0 = Vp[(i + 0) * 128], v1 = Vp[(i + 1) * 128];
            float v2 = Vp[(i + 2) * 128], v3 = Vp[(i + 3) * 128];
            u64 va = pk(v0, v1), vb = pk(v2, v3);
            #pragma unroll
            for (int q = 0; q < QT; q++) {
                ulonglong2 p = *(const ulonglong2*)(Lh + q * LQ + i);
                acc[q] = fma2(p.x, va, acc[q]);
                acc[q] = fma2(p.y, vb, acc[q]);
            }
        }
        float* hpd = hp + (s * 128 + hv) * 11;
        #pragma unroll
        for (int q = 0; q < QT; q++) hpd[q] = hadd(acc[q]);
    }
    __syncthreads();
    if (t < 128) {
        #pragma unroll
        for (int q = 0; q < QT; q++) {
            float v = hp[t * 11 + q] + hp[(128 + t) * 11 + q]
                    + hp[(256 + t) * 11 + q] + hp[(384 + t) * 11 + q];
            headsd[q * 128 + t] = pk(v, v);
        }
    }
    __syncthreads();

    // ---- epilogue: Wo-reuse form. 128 threads: (half of hv) x (e-pair), all 10 q per Wo load ----
    u64* scratch = (u64*)hp;     // 1280 u64 needed, 2816 available
    if (t < 128) {
        int half = t >> 6, ep = t & 63;
        const u64* Wop = (const u64*)Wo + ep;        // row stride 64 u64
        u64 acc[QT];
        #pragma unroll
        for (int q = 0; q < QT; q++) acc[q] = 0ull;
        int hv0 = half * 64;
        for (int hv = hv0; hv < hv0 + 64; hv += 2) {
            u64 w0 = Wop[hv * 64];
            u64 w1 = Wop[(hv + 1) * 64];
            #pragma unroll
            for (int q = 0; q < QT; q++) {
                ulonglong2 hh = *(const ulonglong2*)(headsd + q * 128 + hv);
                acc[q] = fma2(hh.x, w0, acc[q]);
                acc[q] = fma2(hh.y, w1, acc[q]);
            }
        }
        #pragma unroll
        for (int q = 0; q < QT; q++) scratch[t * QT + q] = acc[q];
    }
    __syncthreads();
    if (t < 64) {
        #pragma unroll
        for (int q = 0; q < QT; q++) {
            float2 a = up(scratch[t * QT + q]);
            float2 c = up(scratch[(64 + t) * QT + q]);
            float2 r; r.x = a.x + c.x; r.y = a.y + c.y;
            *(float2*)(out + (size_t)(b * Gn + q0 + q) * 128 + t * 2) = r;
        }
    }
}

extern "C" void kernel_launch(void* const* d_in, const int* in_sizes, int n_in,
                              void* d_out, int out_size) {
    const float* h_em  = (const float*)d_in[0];
    const float* route = (const float*)d_in[1];
    const float* Wq    = (const float*)d_in[2];
    const float* Wk    = (const float*)d_in[3];
    const float* Wv    = (const float*)d_in[4];
    const float* W1    = (const float*)d_in[5];
    const float* b1    = (const float*)d_in[6];
    const float* W2    = (const float*)d_in[7];
    const float* b2    = (const float*)d_in[8];
    const float* Wo    = (const float*)d_in[9];
    float* out = (float*)d_out;

    float* out_route = nullptr;
    if (out_size >= 1638400 + 40960000) out_route = out + 1638400;

    static bool attr_done = false;
    if (!attr_done) {
        cudaFuncSetAttribute(proj_kernel, cudaFuncAttributeMaxDynamicSharedMemorySize, SMEM1);
        cudaFuncSetAttribute(main_kernel, cudaFuncAttributeMaxDynamicSharedMemorySize, SMEM2);
        attr_done = true;
    }

    dim3 grid1(4, Bn, 3);
    proj_kernel<<<grid1, 256, SMEM1>>>(h_em, Wq, Wk, Wv);
    dim3 grid2(Gn / QT, Bn);
    main_kernel<<<grid2, 512, SMEM2>>>(route, W1, b1, W2, b2, Wo, out, out_route);
}